// round 16
// baseline (speedup 1.0000x reference)
#include <cuda_runtime.h>

// WeightedDistanceTransform — champion pipeline: 2-stream slice split (R14) +
// k2 strips widened to 32 cols (full-warp-coalesced stores, 8 CTAs/slice).
// k1: bitmask pack (ballot) -> 1-bit mask scratch
// k2: g^2 on the fly (clz/ffs) + exact early-exit vertical min-plus -> dt + atomicMax
// k3: inverted normalize (mx - dt)/mx.

#define HH 256
#define WW 256
#define NPIX (HH * WW)
#define BIG 512
#define MAXSLICES 64
#define WPR 8
#define SLICE_WORDS (HH * WPR)        // 2048

__device__ unsigned int maskbuf[MAXSLICES * SLICE_WORDS];
__device__ unsigned int mx_bits[MAXSLICES];

// ---------------- Kernel 1: mask pack ----------------
#define K1_THREADS 256

__global__ __launch_bounds__(K1_THREADS)
void k1_mask(const float* __restrict__ in, int slice0) {
    const int slice = slice0 + (blockIdx.x >> 4);
    const int rb    = blockIdx.x & 15;
    const int tid   = threadIdx.x;

    if (rb == 0 && tid == 0) mx_bits[slice] = 0u;        // reset before k2 (same stream)

    const float4* s4 = reinterpret_cast<const float4*>(in)
                     + (size_t)slice * (NPIX / 4) + (size_t)rb * 1024 + tid * 4;
    float4 a = s4[0], b = s4[1], c = s4[2], d = s4[3];
    unsigned m = 0;
    m |= (a.x != 0.0f) << 0;  m |= (a.y != 0.0f) << 1;
    m |= (a.z != 0.0f) << 2;  m |= (a.w != 0.0f) << 3;
    m |= (b.x != 0.0f) << 4;  m |= (b.y != 0.0f) << 5;
    m |= (b.z != 0.0f) << 6;  m |= (b.w != 0.0f) << 7;
    m |= (c.x != 0.0f) << 8;  m |= (c.y != 0.0f) << 9;
    m |= (c.z != 0.0f) << 10; m |= (c.w != 0.0f) << 11;
    m |= (d.x != 0.0f) << 12; m |= (d.y != 0.0f) << 13;
    m |= (d.z != 0.0f) << 14; m |= (d.w != 0.0f) << 15;
    unsigned other = __shfl_xor_sync(0xffffffffu, m, 1);
    if ((tid & 1) == 0) {
        maskbuf[slice * SLICE_WORDS + rb * 128 + (tid >> 1)] = m | (other << 16);
    }
}

// ---------------- Kernel 2: g^2 + vertical min-plus (32-col strips) ----------------
#define K2_COLS 32
#define K2_THREADS 512

__global__ __launch_bounds__(K2_THREADS)
void k2_passB(float* __restrict__ out, int slice0) {
    __shared__ unsigned int M[SLICE_WORDS];       // 8 KB: whole-slice bitmask
    __shared__ unsigned int g2[HH * K2_COLS];     // 32 KB: g^2 tile [row][col]
    __shared__ float red[K2_THREADS / 32];        // 16 warps

    const int slice = slice0 + (blockIdx.x >> 3); // 8 strips per slice
    const int st    = blockIdx.x & 7;
    const int c0    = st * K2_COLS;
    const int tid   = threadIdx.x;

    {
        const unsigned int* src = maskbuf + slice * SLICE_WORDS;
        #pragma unroll
        for (int k = 0; k < SLICE_WORDS / K2_THREADS; ++k)
            M[k * K2_THREADS + tid] = src[k * K2_THREADS + tid];
    }
    __syncthreads();

    // compute g^2 for the strip: 16 px/thread (warp = one row of 32 cols)
    #pragma unroll
    for (int it = 0; it < (HH * K2_COLS) / K2_THREADS; ++it) {
        int i = it * K2_THREADS + tid;
        int r = i >> 5;
        int w = c0 + (i & 31);
        const unsigned int* Mr = M + r * WPR;
        int ci = w >> 5, b = w & 31;

        int ld = BIG;                                          // nearest zero <= w
        unsigned lmask = (b == 31) ? 0xffffffffu : ((2u << b) - 1u);
        unsigned z = (~Mr[ci]) & lmask;
        if (z) {
            ld = b - (31 - __clz(z));
        } else {
            for (int cj = ci - 1; cj >= 0; --cj) {
                unsigned zz = ~Mr[cj];
                if (zz) { ld = (ci - cj) * 32 + b - (31 - __clz(zz)); break; }
            }
        }
        int rd = BIG;                                          // nearest zero >= w
        z = (~Mr[ci]) >> b;
        if (z) {
            rd = __ffs(z) - 1;
        } else {
            for (int cj = ci + 1; cj < WPR; ++cj) {
                unsigned zz = ~Mr[cj];
                if (zz) { rd = cj * 32 + (__ffs(zz) - 1) - w; break; }
            }
        }
        int g = min(min(ld, rd), BIG);
        g2[r * K2_COLS + (i & 31)] = (unsigned)(g * g);
    }
    __syncthreads();

    const float wts[3] = {0.5f, 1.0f, 2.0f};
    const float wc = wts[slice % 3];
    float* dst = out + (size_t)slice * NPIX;

    float lmax = 0.0f;
    #pragma unroll
    for (int it = 0; it < (HH * K2_COLS) / K2_THREADS; ++it) {
        int i = it * K2_THREADS + tid;
        int r = i >> 5, c = i & 31;
        int best = (int)g2[r * K2_COLS + c];
        for (int d = 1; d < HH; ++d) {
            int dd = d * d;
            if (dd >= best) break;                // exact: candidates are >= d^2
            int up = r - d, dn = r + d;
            if (up >= 0) best = min(best, (int)g2[up * K2_COLS + c] + dd);
            if (dn < HH) best = min(best, (int)g2[dn * K2_COLS + c] + dd);
        }
        float dt = wc * sqrtf((float)best);
        dst[r * WW + c0 + c] = dt;                // warp: 32 consecutive floats = 128B
        lmax = fmaxf(lmax, dt);
    }

    #pragma unroll
    for (int o = 16; o; o >>= 1) lmax = fmaxf(lmax, __shfl_xor_sync(0xffffffffu, lmax, o));
    if ((tid & 31) == 0) red[tid >> 5] = lmax;
    __syncthreads();
    if (tid < 16) {
        float v = red[tid];
        #pragma unroll
        for (int o = 8; o; o >>= 1) v = fmaxf(v, __shfl_xor_sync(0x0000ffffu, v, o, 16));
        if (tid == 0) atomicMax(&mx_bits[slice], __float_as_uint(v));  // dt>=0: bit-monotone
    }
}

// ---------------- Kernel 3: normalize ----------------
#define K3_THREADS 256

__global__ __launch_bounds__(K3_THREADS)
void k3_norm(float* __restrict__ out, int slice0) {
    const int slice = slice0 + (blockIdx.x >> 4);
    const int bl    = blockIdx.x & 15;
    const float mx  = __uint_as_float(mx_bits[slice]);
    const float inv = (mx > 0.0f) ? (1.0f / mx) : 0.0f;   // mx==0 -> dt==0 -> out 0

    float4* p = reinterpret_cast<float4*>(out) + (size_t)slice * (NPIX / 4) + bl * 1024;
    #pragma unroll
    for (int k = 0; k < 4; ++k) {
        int j = k * K3_THREADS + threadIdx.x;
        float4 v = p[j];
        v.x = (mx - v.x) * inv;
        v.y = (mx - v.y) * inv;
        v.z = (mx - v.z) * inv;
        v.w = (mx - v.w) * inv;
        p[j] = v;
    }
}

extern "C" void kernel_launch(void* const* d_in, const int* in_sizes, int n_in,
                              void* d_out, int out_size) {
    const float* in = (const float*)d_in[0];
    float* out = (float*)d_out;
    const int nslices = in_sizes[0] / NPIX;       // 48 for [16,3,256,256]

    // One-time side stream + fork/join events (no device memory involved).
    static cudaStream_t sB = nullptr;
    static cudaEvent_t  eFork = nullptr, eJoin = nullptr;
    if (sB == nullptr) {
        cudaStreamCreateWithFlags(&sB, cudaStreamNonBlocking);
        cudaEventCreateWithFlags(&eFork, cudaEventDisableTiming);
        cudaEventCreateWithFlags(&eJoin, cudaEventDisableTiming);
    }

    const int nA = (nslices + 1) / 2;             // group A: [0, nA)
    const int nB = nslices - nA;                  // group B: [nA, nslices)

    if (nB > 0) {
        cudaEventRecord(eFork, 0);
        cudaStreamWaitEvent(sB, eFork, 0);
    }

    k1_mask <<<nA * 16, K1_THREADS, 0, 0>>>(in,  0);
    k2_passB<<<nA * 8,  K2_THREADS, 0, 0>>>(out, 0);
    k3_norm <<<nA * 16, K3_THREADS, 0, 0>>>(out, 0);

    if (nB > 0) {
        k1_mask <<<nB * 16, K1_THREADS, 0, sB>>>(in,  nA);
        k2_passB<<<nB * 8,  K2_THREADS, 0, sB>>>(out, nA);
        k3_norm <<<nB * 16, K3_THREADS, 0, sB>>>(out, nA);

        cudaEventRecord(eJoin, sB);
        cudaStreamWaitEvent(0, eJoin, 0);
    }
}

// round 17
// speedup vs baseline: 1.0844x; 1.0844x over previous
#include <cuda_runtime.h>

// WeightedDistanceTransform — R14 2-stream pipeline + k2 u16-g 32-col strips.
// k1: bitmask pack (ballot) -> 1-bit mask scratch            (verbatim champion)
// k2: 32-col strips, 1024 thr (8 px/thread), g as u16 (16 KB tile, 24 KB total
//     smem = champion footprint); warp = full row -> 128B coalesced dt stores.
// k3: inverted normalize (mx - dt)/mx                        (verbatim champion)

#define HH 256
#define WW 256
#define NPIX (HH * WW)
#define BIG 512
#define MAXSLICES 64
#define WPR 8
#define SLICE_WORDS (HH * WPR)        // 2048

__device__ unsigned int maskbuf[MAXSLICES * SLICE_WORDS];
__device__ unsigned int mx_bits[MAXSLICES];

// ---------------- Kernel 1: mask pack ----------------
#define K1_THREADS 256

__global__ __launch_bounds__(K1_THREADS)
void k1_mask(const float* __restrict__ in, int slice0) {
    const int slice = slice0 + (blockIdx.x >> 4);
    const int rb    = blockIdx.x & 15;
    const int tid   = threadIdx.x;

    if (rb == 0 && tid == 0) mx_bits[slice] = 0u;        // reset before k2 (same stream)

    const float4* s4 = reinterpret_cast<const float4*>(in)
                     + (size_t)slice * (NPIX / 4) + (size_t)rb * 1024 + tid * 4;
    float4 a = s4[0], b = s4[1], c = s4[2], d = s4[3];
    unsigned m = 0;
    m |= (a.x != 0.0f) << 0;  m |= (a.y != 0.0f) << 1;
    m |= (a.z != 0.0f) << 2;  m |= (a.w != 0.0f) << 3;
    m |= (b.x != 0.0f) << 4;  m |= (b.y != 0.0f) << 5;
    m |= (b.z != 0.0f) << 6;  m |= (b.w != 0.0f) << 7;
    m |= (c.x != 0.0f) << 8;  m |= (c.y != 0.0f) << 9;
    m |= (c.z != 0.0f) << 10; m |= (c.w != 0.0f) << 11;
    m |= (d.x != 0.0f) << 12; m |= (d.y != 0.0f) << 13;
    m |= (d.z != 0.0f) << 14; m |= (d.w != 0.0f) << 15;
    unsigned other = __shfl_xor_sync(0xffffffffu, m, 1);
    if ((tid & 1) == 0) {
        maskbuf[slice * SLICE_WORDS + rb * 128 + (tid >> 1)] = m | (other << 16);
    }
}

// ---------------- Kernel 2: g (u16) + vertical min-plus, 32-col strips ----------------
#define K2_COLS 32
#define K2_THREADS 1024

__global__ __launch_bounds__(K2_THREADS)
void k2_passB(float* __restrict__ out, int slice0) {
    __shared__ unsigned int   M[SLICE_WORDS];        // 8 KB: whole-slice bitmask
    __shared__ unsigned short gt[HH * K2_COLS];      // 16 KB: g tile (u16) [row][col]
    __shared__ float red[K2_THREADS / 32];           // 32 warps

    const int slice = slice0 + (blockIdx.x >> 3);    // 8 strips per slice
    const int st    = blockIdx.x & 7;
    const int c0    = st * K2_COLS;
    const int tid   = threadIdx.x;

    {
        const unsigned int* src = maskbuf + slice * SLICE_WORDS;
        #pragma unroll
        for (int k = 0; k < SLICE_WORDS / K2_THREADS; ++k)
            M[k * K2_THREADS + tid] = src[k * K2_THREADS + tid];
    }
    __syncthreads();

    // compute g for the strip: 8 px/thread (warp = one row of 32 cols)
    #pragma unroll
    for (int it = 0; it < (HH * K2_COLS) / K2_THREADS; ++it) {
        int i = it * K2_THREADS + tid;
        int r = i >> 5;
        int w = c0 + (i & 31);
        const unsigned int* Mr = M + r * WPR;
        int ci = w >> 5, b = w & 31;

        int ld = BIG;                                          // nearest zero <= w
        unsigned lmask = (b == 31) ? 0xffffffffu : ((2u << b) - 1u);
        unsigned z = (~Mr[ci]) & lmask;
        if (z) {
            ld = b - (31 - __clz(z));
        } else {
            for (int cj = ci - 1; cj >= 0; --cj) {
                unsigned zz = ~Mr[cj];
                if (zz) { ld = (ci - cj) * 32 + b - (31 - __clz(zz)); break; }
            }
        }
        int rd = BIG;                                          // nearest zero >= w
        z = (~Mr[ci]) >> b;
        if (z) {
            rd = __ffs(z) - 1;
        } else {
            for (int cj = ci + 1; cj < WPR; ++cj) {
                unsigned zz = ~Mr[cj];
                if (zz) { rd = cj * 32 + (__ffs(zz) - 1) - w; break; }
            }
        }
        gt[r * K2_COLS + (i & 31)] = (unsigned short)min(min(ld, rd), BIG);
    }
    __syncthreads();

    const float wts[3] = {0.5f, 1.0f, 2.0f};
    const float wc = wts[slice % 3];
    float* dst = out + (size_t)slice * NPIX;

    float lmax = 0.0f;
    #pragma unroll
    for (int it = 0; it < (HH * K2_COLS) / K2_THREADS; ++it) {
        int i = it * K2_THREADS + tid;
        int r = i >> 5, c = i & 31;
        int g0   = (int)gt[r * K2_COLS + c];
        int best = g0 * g0;
        for (int d = 1; d < HH; ++d) {
            int dd = d * d;
            if (dd >= best) break;                // exact: candidates are >= d^2
            int up = r - d, dn = r + d;
            if (up >= 0) { int cu = (int)gt[up * K2_COLS + c]; best = min(best, cu * cu + dd); }
            if (dn < HH) { int cd = (int)gt[dn * K2_COLS + c]; best = min(best, cd * cd + dd); }
        }
        float dt = wc * sqrtf((float)best);
        dst[r * WW + c0 + c] = dt;                // warp: 32 consecutive floats = 128B
        lmax = fmaxf(lmax, dt);
    }

    #pragma unroll
    for (int o = 16; o; o >>= 1) lmax = fmaxf(lmax, __shfl_xor_sync(0xffffffffu, lmax, o));
    if ((tid & 31) == 0) red[tid >> 5] = lmax;
    __syncthreads();
    if (tid < 32) {
        float v = red[tid];
        #pragma unroll
        for (int o = 16; o; o >>= 1) v = fmaxf(v, __shfl_xor_sync(0xffffffffu, v, o));
        if (tid == 0) atomicMax(&mx_bits[slice], __float_as_uint(v));  // dt>=0: bit-monotone
    }
}

// ---------------- Kernel 3: normalize ----------------
#define K3_THREADS 256

__global__ __launch_bounds__(K3_THREADS)
void k3_norm(float* __restrict__ out, int slice0) {
    const int slice = slice0 + (blockIdx.x >> 4);
    const int bl    = blockIdx.x & 15;
    const float mx  = __uint_as_float(mx_bits[slice]);
    const float inv = (mx > 0.0f) ? (1.0f / mx) : 0.0f;   // mx==0 -> dt==0 -> out 0

    float4* p = reinterpret_cast<float4*>(out) + (size_t)slice * (NPIX / 4) + bl * 1024;
    #pragma unroll
    for (int k = 0; k < 4; ++k) {
        int j = k * K3_THREADS + threadIdx.x;
        float4 v = p[j];
        v.x = (mx - v.x) * inv;
        v.y = (mx - v.y) * inv;
        v.z = (mx - v.z) * inv;
        v.w = (mx - v.w) * inv;
        p[j] = v;
    }
}

extern "C" void kernel_launch(void* const* d_in, const int* in_sizes, int n_in,
                              void* d_out, int out_size) {
    const float* in = (const float*)d_in[0];
    float* out = (float*)d_out;
    const int nslices = in_sizes[0] / NPIX;       // 48 for [16,3,256,256]

    // One-time side stream + fork/join events (no device memory involved).
    static cudaStream_t sB = nullptr;
    static cudaEvent_t  eFork = nullptr, eJoin = nullptr;
    if (sB == nullptr) {
        cudaStreamCreateWithFlags(&sB, cudaStreamNonBlocking);
        cudaEventCreateWithFlags(&eFork, cudaEventDisableTiming);
        cudaEventCreateWithFlags(&eJoin, cudaEventDisableTiming);
    }

    const int nA = (nslices + 1) / 2;             // group A: [0, nA)
    const int nB = nslices - nA;                  // group B: [nA, nslices)

    if (nB > 0) {
        cudaEventRecord(eFork, 0);
        cudaStreamWaitEvent(sB, eFork, 0);
    }

    k1_mask <<<nA * 16, K1_THREADS, 0, 0>>>(in,  0);
    k2_passB<<<nA * 8,  K2_THREADS, 0, 0>>>(out, 0);
    k3_norm <<<nA * 16, K3_THREADS, 0, 0>>>(out, 0);

    if (nB > 0) {
        k1_mask <<<nB * 16, K1_THREADS, 0, sB>>>(in,  nA);
        k2_passB<<<nB * 8,  K2_THREADS, 0, sB>>>(out, nA);
        k3_norm <<<nB * 16, K3_THREADS, 0, sB>>>(out, nA);

        cudaEventRecord(eJoin, sB);
        cudaStreamWaitEvent(0, eJoin, 0);
    }
}